// round 1
// baseline (speedup 1.0000x reference)
#include <cuda_runtime.h>

#define A_   50
#define T_   50
#define HID_ 128
#define H_   32
#define C_   16
#define B_   32
#define S_   2450          // T_*(A_-1)
#define HC_  512           // H_*C_
#define NEG_SLOPE 0.2f

// ---------------- scratch (device globals; no allocations allowed) --------
__device__ float g_xw[(size_t)B_ * H_ * S_ * C_];   // [b][h][s][c]  160.6 MB
__device__ float g_asrc[B_ * H_ * S_];              // [b][h][s]
__device__ float g_adst[B_ * H_ * T_];              // [b][h][t]
__device__ float g_Wt[HID_ * HC_];                  // [k][n]  (W transposed)
__device__ float g_vdst[H_ * HID_];                 // [h][d]  = sum_c W[h,c,d]*att_dst[h,c]

// ---------------- prep: transpose W, contract att_dst into v_dst ----------
__global__ void prep_kernel(const float* __restrict__ W,
                            const float* __restrict__ att_dst) {
    int idx = blockIdx.x * blockDim.x + threadIdx.x;
    if (idx < HID_ * HC_) {
        int k = idx / HC_, n = idx % HC_;
        g_Wt[idx] = W[n * HID_ + k];
    }
    if (idx < H_ * HID_) {
        int h = idx / HID_, d = idx % HID_;
        float s2 = 0.f;
        #pragma unroll
        for (int c = 0; c < C_; c++)
            s2 += W[(h * C_ + c) * HID_ + d] * att_dst[h * C_ + c];
        g_vdst[idx] = s2;
    }
}

// ---------------- GEMM: xw[b,h,s,c] = X[b,s,:] . W[h*16+c,:]  + a_src epilogue
// BM=64 (s), BN=64 (4 heads), K=128 in 2 chunks of 64. 256 threads, 4x4 micro.
__global__ __launch_bounds__(256) void gemm_kernel(const float* __restrict__ hin,
                                                   const float* __restrict__ att_src) {
    __shared__ float As[64][68];   // [row(s)][k]   pad 68: conflict-free, f4-aligned
    __shared__ float Bs[64][64];   // [k][col(n)]

    int b  = blockIdx.z;
    int s0 = blockIdx.y * 64;
    int n0 = blockIdx.x * 64;
    int tid = threadIdx.x;
    int tx = tid & 15, ty = tid >> 4;

    float acc[4][4] = {};

    for (int kc = 0; kc < 2; kc++) {
        int k0 = kc * 64;
        // load X tile (rows are scattered h[b, a, t, :] rows; each 512B contiguous)
        #pragma unroll
        for (int i = 0; i < 4; i++) {
            int slot = tid + 256 * i;
            int row = slot >> 4, k4 = slot & 15;
            int s = s0 + row;
            float4 v = make_float4(0.f, 0.f, 0.f, 0.f);
            if (s < S_) {
                int a = s % 49 + 1;           // ne = [1..49] (EGO=0)
                int t = s / 49;
                v = *(const float4*)&hin[(((b * A_ + a) * T_ + t) * HID_) + k0 + k4 * 4];
            }
            *(float4*)&As[row][k4 * 4] = v;
        }
        // load W tile from pre-transposed Wt (fully coalesced)
        #pragma unroll
        for (int i = 0; i < 4; i++) {
            int slot = tid + 256 * i;
            int k = slot >> 4, c4 = slot & 15;
            *(float4*)&Bs[k][c4 * 4] = *(const float4*)&g_Wt[(k0 + k) * HC_ + n0 + c4 * 4];
        }
        __syncthreads();

        #pragma unroll 16
        for (int k = 0; k < 64; k++) {
            float av0 = As[ty * 4 + 0][k];
            float av1 = As[ty * 4 + 1][k];
            float av2 = As[ty * 4 + 2][k];
            float av3 = As[ty * 4 + 3][k];
            float4 bv = *(float4*)&Bs[k][tx * 4];
            acc[0][0] += av0 * bv.x; acc[0][1] += av0 * bv.y; acc[0][2] += av0 * bv.z; acc[0][3] += av0 * bv.w;
            acc[1][0] += av1 * bv.x; acc[1][1] += av1 * bv.y; acc[1][2] += av1 * bv.z; acc[1][3] += av1 * bv.w;
            acc[2][0] += av2 * bv.x; acc[2][1] += av2 * bv.y; acc[2][2] += av2 * bv.z; acc[2][3] += av2 * bv.w;
            acc[3][0] += av3 * bv.x; acc[3][1] += av3 * bv.y; acc[3][2] += av3 * bv.z; acc[3][3] += av3 * bv.w;
        }
        __syncthreads();
    }

    // epilogue: store xw (layout [b][h][s][c]) + reduce a_src for free
    int col0 = n0 + tx * 4;
    int hh = col0 >> 4;        // head (4 consecutive cols stay in one head)
    int c0 = col0 & 15;
    float asv[4];
    #pragma unroll
    for (int j = 0; j < 4; j++) asv[j] = __ldg(&att_src[hh * C_ + c0 + j]);

    #pragma unroll
    for (int i = 0; i < 4; i++) {
        int s = s0 + ty * 4 + i;
        float part = acc[i][0] * asv[0] + acc[i][1] * asv[1] +
                     acc[i][2] * asv[2] + acc[i][3] * asv[3];
        // the 4 lanes (tx%4 == 0..3) of one head share the same s
        part += __shfl_xor_sync(0xffffffffu, part, 1);
        part += __shfl_xor_sync(0xffffffffu, part, 2);
        if (s < S_) {
            size_t base = ((size_t)(b * H_ + hh) * S_ + s) * C_ + c0;
            *(float4*)&g_xw[base] = make_float4(acc[i][0], acc[i][1], acc[i][2], acc[i][3]);
            if ((tx & 3) == 0)
                g_asrc[(b * H_ + hh) * S_ + s] = part;
        }
    }
}

// ---------------- a_dst_ego[b,h,t] = h[b,0,t,:] . v_dst[h,:] ---------------
__global__ __launch_bounds__(256) void adst_kernel(const float* __restrict__ hin) {
    __shared__ float hs[T_][HID_];       // 25.6 KB
    __shared__ float vd[H_ * 129];       // pad 129 -> conflict-free per-lane h
    int b = blockIdx.x;
    int tid = threadIdx.x;

    for (int idx = tid; idx < T_ * HID_; idx += 256) {
        int t = idx / HID_, d = idx % HID_;
        hs[t][d] = hin[((b * A_ + 0) * T_ + t) * HID_ + d];
    }
    for (int idx = tid; idx < H_ * HID_; idx += 256) {
        int h = idx / HID_, d = idx % HID_;
        vd[h * 129 + d] = g_vdst[idx];
    }
    __syncthreads();

    int h = tid & 31;
    for (int t = tid >> 5; t < T_; t += 8) {
        float acc = 0.f;
        #pragma unroll 16
        for (int d = 0; d < HID_; d++)
            acc += hs[t][d] * vd[h * 129 + d];
        g_adst[(b * H_ + h) * T_ + t] = acc;
    }
}

// ---------------- fill entire output with broadcast bias -------------------
__global__ void fill_kernel(float* __restrict__ out, const float* __restrict__ bias, int n4) {
    int idx = blockIdx.x * blockDim.x + threadIdx.x;
    int stride = gridDim.x * blockDim.x;
    for (; idx < n4; idx += stride)
        ((float4*)out)[idx] = ((const float4*)bias)[idx & 127];
}

// ---------------- attention: softmax over s (factored exp) + att @ x_ne ----
__global__ __launch_bounds__(256) void attn_kernel(float* __restrict__ out,
                                                   const float* __restrict__ bias) {
    __shared__ float p1[S_], p2[S_];          // exp(a_s), exp(0.2 a_s)
    __shared__ float dd[T_], eth[T_], w1[T_], w2[T_];
    __shared__ float att[T_][68];             // att tile [t][ss], pad 68
    __shared__ float xsT[C_][68];             // x chunk transposed [c][ss]

    int hh = blockIdx.x;
    int b  = blockIdx.y;
    int tid = threadIdx.x;
    const float* asrc = g_asrc + (b * H_ + hh) * S_;

    for (int s = tid; s < S_; s += 256) {
        float a = asrc[s];
        p1[s] = __expf(a);
        p2[s] = __expf(NEG_SLOPE * a);
    }
    if (tid < T_) {
        float d = g_adst[(b * H_ + hh) * T_ + tid];
        dd[tid]  = d;
        eth[tid] = __expf(-d);                // a_s > -d  <=>  p1[s] > eth[t]
    }
    __syncthreads();

    // Z per target t (warp-per-t round robin)
    int lane = tid & 31, w = tid >> 5;
    for (int t = w; t < T_; t += 8) {
        float et = eth[t];
        float a1 = 0.f, a2 = 0.f;
        for (int s = lane; s < S_; s += 32) {
            float q1 = p1[s];
            if (q1 > et) a1 += q1; else a2 += p2[s];
        }
        #pragma unroll
        for (int o = 16; o; o >>= 1) {
            a1 += __shfl_xor_sync(0xffffffffu, a1, o);
            a2 += __shfl_xor_sync(0xffffffffu, a2, o);
        }
        if (lane == 0) {
            float d = dd[t];
            float e1 = __expf(d), e2 = __expf(NEG_SLOPE * d);
            float Z = e1 * a1 + e2 * a2;
            w1[t] = e1 / Z;
            w2[t] = e2 / Z;
        }
    }
    __syncthreads();

    // out[t, c] = sum_s att[t,s] * x_ne[s,c]   (chunks of 64 s)
    int tx = tid & 15, ty = tid >> 4;
    float acc[4] = {0.f, 0.f, 0.f, 0.f};
    const float* xw = g_xw + (size_t)(b * H_ + hh) * S_ * C_;

    for (int s0 = 0; s0 < S_; s0 += 64) {
        // load x chunk, transposed into [c][ss]
        {
            int row = tid >> 2, cq = tid & 3;
            float4 v = make_float4(0.f, 0.f, 0.f, 0.f);
            if (s0 + row < S_)
                v = *(const float4*)&xw[(size_t)(s0 + row) * C_ + cq * 4];
            xsT[cq * 4 + 0][row] = v.x;
            xsT[cq * 4 + 1][row] = v.y;
            xsT[cq * 4 + 2][row] = v.z;
            xsT[cq * 4 + 3][row] = v.w;
        }
        // build att tile
        {
            int ss = tid & 63;
            int s = s0 + ss;
            float q1 = 0.f, q2 = 0.f;
            if (s < S_) { q1 = p1[s]; q2 = p2[s]; }
            for (int t = tid >> 6; t < T_; t += 4)
                att[t][ss] = (q1 > eth[t]) ? q1 * w1[t] : q2 * w2[t];
        }
        __syncthreads();

        #pragma unroll
        for (int j = 0; j < 4; j++) {
            int t = ty + 16 * j;
            if (t < T_) {
                float a = acc[j];
                #pragma unroll
                for (int q = 0; q < 16; q++) {
                    float4 xv = *(float4*)&xsT[tx][q * 4];
                    float4 av = *(float4*)&att[t][q * 4];
                    a += av.x * xv.x + av.y * xv.y + av.z * xv.z + av.w * xv.w;
                }
                acc[j] = a;
            }
        }
        __syncthreads();
    }

    float bb = __ldg(&bias[hh * C_ + tx]);
    #pragma unroll
    for (int j = 0; j < 4; j++) {
        int t = ty + 16 * j;
        if (t < T_)
            out[((size_t)(b * A_ + 0) * T_ + t) * HC_ + hh * C_ + tx] = acc[j] + bb;
    }
}

// ---------------------------------------------------------------------------
extern "C" void kernel_launch(void* const* d_in, const int* in_sizes, int n_in,
                              void* d_out, int out_size) {
    const float* hin     = (const float*)d_in[0];
    const float* W       = (const float*)d_in[1];
    const float* att_src = (const float*)d_in[2];
    const float* att_dst = (const float*)d_in[3];
    const float* bias    = (const float*)d_in[4];
    float* out = (float*)d_out;

    prep_kernel<<<(HID_ * HC_ + 255) / 256, 256>>>(W, att_dst);

    dim3 g2(HC_ / 64, (S_ + 63) / 64, B_);
    gemm_kernel<<<g2, 256>>>(hin, att_src);

    adst_kernel<<<B_, 256>>>(hin);

    fill_kernel<<<2048, 256>>>(out, bias, out_size / 4);

    dim3 g4(H_, B_);
    attn_kernel<<<g4, 256>>>(out, bias);
}

// round 4
// speedup vs baseline: 1.2721x; 1.2721x over previous
#include <cuda_runtime.h>
#include <cuda_bf16.h>
#include <cstdint>

#define A_   50
#define T_   50
#define HID_ 128
#define H_   32
#define C_   16
#define B_   32
#define S_   2450          // T_*(A_-1)
#define HC_  512           // H_*C_
#define NEG_SLOPE 0.2f

// ---------------- scratch (device globals; no allocations allowed) --------
// g_xw layout: float4 units, index ((b*H+h)*4 + c4)*S_ + s  (c = c4*4+0..3)
__device__ __align__(16) float g_xw[(size_t)B_ * H_ * 4 * S_ * 4];
__device__ float g_asrc[B_ * H_ * S_];              // [b][h][s]
__device__ float g_adst[B_ * H_ * T_];              // [b][h][t]
__device__ float g_vdst[H_ * HID_];                 // [h][d]
__device__ __align__(16) __nv_bfloat16 g_Whi[HC_ * HID_];   // [n][k]
__device__ __align__(16) __nv_bfloat16 g_Wlo[HC_ * HID_];   // [n][k]

__device__ __forceinline__ uint32_t pack_bf16(float a, float b) {
    __nv_bfloat162 t = __floats2bfloat162_rn(a, b);
    return *reinterpret_cast<uint32_t*>(&t);
}

// mma.sync m16n8k16 row.col f32.bf16.bf16.f32  (plain sm_80+ feature, no 'a' needed)
__device__ __forceinline__ void mma_bf16(float* c, const uint32_t* a, const uint32_t* b) {
    asm volatile(
        "mma.sync.aligned.m16n8k16.row.col.f32.bf16.bf16.f32 "
        "{%0,%1,%2,%3}, {%4,%5,%6,%7}, {%8,%9}, {%0,%1,%2,%3};"
        : "+f"(c[0]), "+f"(c[1]), "+f"(c[2]), "+f"(c[3])
        : "r"(a[0]), "r"(a[1]), "r"(a[2]), "r"(a[3]), "r"(b[0]), "r"(b[1]));
}

// ---- dynamic smem layout for GEMM (bytes) ----
// A/W tiles: 128 rows x 136 bf16 (272B stride: LDS bank = lane, conflict-free)
#define ASTR   136
#define OFF_ASC   0                        // att_src cache, 2048B
#define OFF_AHI   2048
#define OFF_ALO   (OFF_AHI + 34816)        // 36864
#define OFF_WHI   (OFF_ALO + 34816)        // 71680
#define OFF_WLO   (OFF_WHI + 34816)        // 106496
#define SMEM_GEMM (OFF_WLO + 34816)        // 141312
#define OFF_OUT   OFF_AHI                  // epilogue reuses A region (67584B <= 69632B)
#define OSTR      132                      // f32 stride for out tile

// ---------------- prep: bf16-split W, contract att_dst into v_dst ----------
__global__ void prep_kernel(const float* __restrict__ W,
                            const float* __restrict__ att_dst) {
    int idx = blockIdx.x * blockDim.x + threadIdx.x;
    if (idx < HID_ * HC_) {
        float w = W[idx];
        __nv_bfloat16 hi = __float2bfloat16(w);
        g_Whi[idx] = hi;
        g_Wlo[idx] = __float2bfloat16(w - __bfloat162float(hi));
    }
    if (idx < H_ * HID_) {
        int h = idx / HID_, d = idx % HID_;
        float s2 = 0.f;
        #pragma unroll
        for (int c = 0; c < C_; c++)
            s2 += W[(h * C_ + c) * HID_ + d] * att_dst[h * C_ + c];
        g_vdst[idx] = s2;
    }
}

// ---------------- mma.sync GEMM: xw = X . W^T  (bf16x3), + a_src epilogue --
// CTA: M=128 s-rows x N=128 cols (8 heads), K=128. 256 threads = 8 warps,
// warp tile 32(m) x 64(n).
__global__ __launch_bounds__(256) void gemm_mma_kernel(const float* __restrict__ hin,
                                                       const float* __restrict__ att_src) {
    extern __shared__ char smem[];
    float* asc = (float*)(smem + OFF_ASC);
    int tid = threadIdx.x, wid = tid >> 5, lane = tid & 31;
    int b = blockIdx.z;
    int s0 = blockIdx.y * 128;
    int n0 = blockIdx.x * 128;           // global col base (8 heads)

    for (int i = tid; i < HC_; i += 256) asc[i] = att_src[i];

    // ---- load + split-convert A tile (X rows) ----
    #pragma unroll
    for (int i = 0; i < 16; i++) {
        int slot = tid + 256 * i;        // 4096 float4 slots
        int row = slot >> 5, k4 = slot & 31;
        int s = s0 + row;
        float4 v = make_float4(0.f, 0.f, 0.f, 0.f);
        if (s < S_) {
            int a = s % 49 + 1, t = s / 49;
            v = *(const float4*)&hin[(((b * A_ + a) * T_ + t) * HID_) + k4 * 4];
        }
        float hx = __bfloat162float(__float2bfloat16(v.x));
        float hy = __bfloat162float(__float2bfloat16(v.y));
        float hz = __bfloat162float(__float2bfloat16(v.z));
        float hw = __bfloat162float(__float2bfloat16(v.w));
        uint2 hv = make_uint2(pack_bf16(v.x, v.y), pack_bf16(v.z, v.w));
        uint2 lv = make_uint2(pack_bf16(v.x - hx, v.y - hy), pack_bf16(v.z - hz, v.w - hw));
        size_t off = (size_t)(row * ASTR + k4 * 4) * 2;
        *(uint2*)(smem + OFF_AHI + off) = hv;
        *(uint2*)(smem + OFF_ALO + off) = lv;
    }
    // ---- load W tiles (bf16 pre-split in global) ----
    #pragma unroll
    for (int i = 0; i < 8; i++) {
        int slot = tid + 256 * i;        // 2048 uint4 slots (8 halves each)
        int row = slot >> 4, k8 = slot & 15;
        size_t off = (size_t)(row * ASTR + k8 * 8) * 2;
        *(uint4*)(smem + OFF_WHI + off) = *(const uint4*)&g_Whi[(n0 + row) * HID_ + k8 * 8];
        *(uint4*)(smem + OFF_WLO + off) = *(const uint4*)&g_Wlo[(n0 + row) * HID_ + k8 * 8];
    }
    __syncthreads();

    // ---- mma mainloop ----
    int wm = wid & 3, wn = wid >> 2;     // m0 = wm*32, n_off = wn*64
    int at = lane >> 2, kq = (lane & 3) * 2;
    float acc[2][8][4];
    #pragma unroll
    for (int mt = 0; mt < 2; mt++)
        #pragma unroll
        for (int nt = 0; nt < 8; nt++)
            #pragma unroll
            for (int j = 0; j < 4; j++) acc[mt][nt][j] = 0.f;

    const uint16_t* Ah = (const uint16_t*)(smem + OFF_AHI);
    const uint16_t* Al = (const uint16_t*)(smem + OFF_ALO);
    const uint16_t* Wh = (const uint16_t*)(smem + OFF_WHI);
    const uint16_t* Wl = (const uint16_t*)(smem + OFF_WLO);

    #pragma unroll
    for (int ks = 0; ks < 8; ks++) {
        int k0 = ks * 16;
        uint32_t ah[2][4], al[2][4], bh[8][2], bl[8][2];
        #pragma unroll
        for (int mt = 0; mt < 2; mt++) {
            int r = wm * 32 + mt * 16 + at;
            int base0 = r * ASTR + k0 + kq;
            int base1 = (r + 8) * ASTR + k0 + kq;
            ah[mt][0] = *(const uint32_t*)&Ah[base0];
            ah[mt][1] = *(const uint32_t*)&Ah[base1];
            ah[mt][2] = *(const uint32_t*)&Ah[base0 + 8];
            ah[mt][3] = *(const uint32_t*)&Ah[base1 + 8];
            al[mt][0] = *(const uint32_t*)&Al[base0];
            al[mt][1] = *(const uint32_t*)&Al[base1];
            al[mt][2] = *(const uint32_t*)&Al[base0 + 8];
            al[mt][3] = *(const uint32_t*)&Al[base1 + 8];
        }
        #pragma unroll
        for (int nt = 0; nt < 8; nt++) {
            int n = wn * 64 + nt * 8 + at;
            int base = n * ASTR + k0 + kq;
            bh[nt][0] = *(const uint32_t*)&Wh[base];
            bh[nt][1] = *(const uint32_t*)&Wh[base + 8];
            bl[nt][0] = *(const uint32_t*)&Wl[base];
            bl[nt][1] = *(const uint32_t*)&Wl[base + 8];
        }
        #pragma unroll
        for (int mt = 0; mt < 2; mt++)
            #pragma unroll
            for (int nt = 0; nt < 8; nt++) {
                mma_bf16(acc[mt][nt], ah[mt], bh[nt]);   // hi*hi
                mma_bf16(acc[mt][nt], ah[mt], bl[nt]);   // hi*lo
                mma_bf16(acc[mt][nt], al[mt], bh[nt]);   // lo*hi
            }
    }
    __syncthreads();                       // done reading A/B; reuse region

    // ---- stage D in smem (stride OSTR) ----
    float* outs = (float*)(smem + OFF_OUT);
    #pragma unroll
    for (int mt = 0; mt < 2; mt++) {
        int r = wm * 32 + mt * 16 + at;
        #pragma unroll
        for (int nt = 0; nt < 8; nt++) {
            int cc = wn * 64 + nt * 8 + kq;
            *(float2*)&outs[r * OSTR + cc]       = make_float2(acc[mt][nt][0], acc[mt][nt][1]);
            *(float2*)&outs[(r + 8) * OSTR + cc] = make_float2(acc[mt][nt][2], acc[mt][nt][3]);
        }
    }
    __syncthreads();

    // ---- write g_xw (coalesced: lane == s) ----
    #pragma unroll
    for (int i = 0; i < 16; i++) {
        int slot = tid + 256 * i;          // 4096 = 128 rows x 32 col-quads
        int srow = slot & 127, g = slot >> 7;   // g: 0..31 = (h_local*4 + c4)
        int s = s0 + srow;
        if (s < S_) {
            int h_local = g >> 2, c4 = g & 3;
            float4 v = *(float4*)&outs[srow * OSTR + g * 4];
            ((float4*)g_xw)[((size_t)((b * H_ + (n0 >> 4) + h_local) * 4 + c4)) * S_ + s] = v;
        }
    }
    // ---- a_src reduction ----
    #pragma unroll
    for (int i = 0; i < 4; i++) {
        int slot = tid + 256 * i;          // 1024 = 128 rows x 8 heads
        int srow = slot & 127, h_local = slot >> 7;
        int s = s0 + srow;
        int hg = (n0 >> 4) + h_local;
        float dot = 0.f;
        #pragma unroll
        for (int cq = 0; cq < 4; cq++) {
            float4 v = *(float4*)&outs[srow * OSTR + h_local * 16 + cq * 4];
            float4 w = *(float4*)&asc[hg * C_ + cq * 4];
            dot += v.x * w.x + v.y * w.y + v.z * w.z + v.w * w.w;
        }
        if (s < S_) g_asrc[(b * H_ + hg) * S_ + s] = dot;
    }
}

// ---------------- a_dst_ego[b,h,t] = h[b,0,t,:] . v_dst[h,:] ---------------
__global__ __launch_bounds__(256) void adst_kernel(const float* __restrict__ hin) {
    __shared__ float hs[T_][HID_];
    __shared__ float vd[H_ * 129];
    int b = blockIdx.x;
    int tid = threadIdx.x;

    for (int idx = tid; idx < T_ * HID_; idx += 256) {
        int t = idx / HID_, d = idx % HID_;
        hs[t][d] = hin[((b * A_ + 0) * T_ + t) * HID_ + d];
    }
    for (int idx = tid; idx < H_ * HID_; idx += 256) {
        int h = idx / HID_, d = idx % HID_;
        vd[h * 129 + d] = g_vdst[idx];
    }
    __syncthreads();

    int h = tid & 31;
    for (int t = tid >> 5; t < T_; t += 8) {
        float acc = 0.f;
        #pragma unroll 16
        for (int d = 0; d < HID_; d++)
            acc += hs[t][d] * vd[h * 129 + d];
        g_adst[(b * H_ + h) * T_ + t] = acc;
    }
}

// ---------------- fill entire output with broadcast bias -------------------
__global__ void fill_kernel(float* __restrict__ out, const float* __restrict__ bias, int n4) {
    int idx = blockIdx.x * blockDim.x + threadIdx.x;
    int stride = gridDim.x * blockDim.x;
    for (; idx < n4; idx += stride)
        ((float4*)out)[idx] = ((const float4*)bias)[idx & 127];
}

// ---------------- attention: factored softmax + att @ x_ne ----------------
__global__ __launch_bounds__(256) void attn_kernel(float* __restrict__ out,
                                                   const float* __restrict__ bias) {
    __shared__ float p1[S_], p2[S_];
    __shared__ float dd[T_], eth[T_], w1[T_], w2[T_];
    __shared__ float att[64][68];             // padded to 64 t-rows
    __shared__ float xsT[C_][68];

    int hh = blockIdx.x;
    int b  = blockIdx.y;
    int tid = threadIdx.x;
    const float* asrc = g_asrc + (b * H_ + hh) * S_;

    for (int s = tid; s < S_; s += 256) {
        float a = asrc[s];
        p1[s] = __expf(a);
        p2[s] = __expf(NEG_SLOPE * a);
    }
    if (tid < T_) {
        float d = g_adst[(b * H_ + hh) * T_ + tid];
        dd[tid]  = d;
        eth[tid] = __expf(-d);
    }
    __syncthreads();

    int lane = tid & 31, w = tid >> 5;
    for (int t = w; t < T_; t += 8) {
        float et = eth[t];
        float a1 = 0.f, a2 = 0.f;
        for (int s = lane; s < S_; s += 32) {
            float q1 = p1[s];
            if (q1 > et) a1 += q1; else a2 += p2[s];
        }
        #pragma unroll
        for (int o = 16; o; o >>= 1) {
            a1 += __shfl_xor_sync(0xffffffffu, a1, o);
            a2 += __shfl_xor_sync(0xffffffffu, a2, o);
        }
        if (lane == 0) {
            float d = dd[t];
            float e1 = __expf(d), e2 = __expf(NEG_SLOPE * d);
            float Z = e1 * a1 + e2 * a2;
            w1[t] = e1 / Z;
            w2[t] = e2 / Z;
        }
    }
    __syncthreads();

    int tx = tid & 15, ty = tid >> 4;
    float acc[4] = {0.f, 0.f, 0.f, 0.f};
    const float4* xw4 = (const float4*)g_xw + (size_t)(b * H_ + hh) * 4 * S_;

    for (int s0 = 0; s0 < S_; s0 += 64) {
        {   // load x chunk [64 s][16 c] transposed (coalesced layout)
            int cq = tid >> 6, row = tid & 63;
            int s = s0 + row;
            float4 v = make_float4(0.f, 0.f, 0.f, 0.f);
            if (s < S_) v = xw4[(size_t)cq * S_ + s];
            xsT[cq * 4 + 0][row] = v.x;
            xsT[cq * 4 + 1][row] = v.y;
            xsT[cq * 4 + 2][row] = v.z;
            xsT[cq * 4 + 3][row] = v.w;
        }
        {   // build att tile (rows >= T_ zeroed)
            int ss = tid & 63;
            int s = s0 + ss;
            float q1 = 0.f, q2 = 0.f;
            if (s < S_) { q1 = p1[s]; q2 = p2[s]; }
            for (int t = tid >> 6; t < 64; t += 4)
                att[t][ss] = (t < T_) ? ((q1 > eth[t]) ? q1 * w1[t] : q2 * w2[t]) : 0.f;
        }
        __syncthreads();

        #pragma unroll
        for (int q = 0; q < 16; q++) {
            float4 xv = *(float4*)&xsT[tx][q * 4];
            #pragma unroll
            for (int j = 0; j < 4; j++) {
                int t = ty + 16 * j;
                float4 av = *(float4*)&att[t][q * 4];
                acc[j] += av.x * xv.x + av.y * xv.y + av.z * xv.z + av.w * xv.w;
            }
        }
        __syncthreads();
    }

    float bb = __ldg(&bias[hh * C_ + tx]);
    #pragma unroll
    for (int j = 0; j < 4; j++) {
        int t = ty + 16 * j;
        if (t < T_)
            out[((size_t)(b * A_ + 0) * T_ + t) * HC_ + hh * C_ + tx] = acc[j] + bb;
    }
}

// ---------------------------------------------------------------------------
extern "C" void kernel_launch(void* const* d_in, const int* in_sizes, int n_in,
                              void* d_out, int out_size) {
    const float* hin     = (const float*)d_in[0];
    const float* W       = (const float*)d_in[1];
    const float* att_src = (const float*)d_in[2];
    const float* att_dst = (const float*)d_in[3];
    const float* bias    = (const float*)d_in[4];
    float* out = (float*)d_out;

    static bool attr_done = false;
    if (!attr_done) {
        cudaFuncSetAttribute(gemm_mma_kernel, cudaFuncAttributeMaxDynamicSharedMemorySize, SMEM_GEMM);
        attr_done = true;
    }

    prep_kernel<<<(HID_ * HC_ + 255) / 256, 256>>>(W, att_dst);

    dim3 g2(HC_ / 128, (S_ + 127) / 128, B_);
    gemm_mma_kernel<<<g2, 256, SMEM_GEMM>>>(hin, att_src);

    adst_kernel<<<B_, 256>>>(hin);

    fill_kernel<<<2048, 256>>>(out, bias, out_size / 4);

    dim3 g4(H_, B_);
    attn_kernel<<<g4, 256>>>(out, bias);
}